// round 12
// baseline (speedup 1.0000x reference)
#include <cuda_runtime.h>
#include <cstdint>

// out[0:100]   = dot(I[row,:], p), row = inds1[m,0]*28 + inds1[m,1]
// out[100:200] = dot(J[row,:], p), P = 50000.
//
// v11: 32-byte ld.global.nc.L2::evict_last.v4.b64 streaming loads (ptxas on
// sm_103a only accepts evict_last with 256-bit vectors). Halves LDG count
// and hints L2 to keep the 40MB row set resident across graph replays.
// Structure: 4 rows/block, SPLIT=8, 400 blocks x 256thr @ occ4 (single wave),
// fused last-block reduction.

#define P_DIM     50000
#define P_VEC8    (P_DIM / 8)       // 6250 float8 per row
#define SPLIT     8
#define CARD2     100
#define NOUT      (2 * CARD2)       // 200
#define RPB       4                 // rows per block
#define NGROUPS   (NOUT / RPB)      // 50
#define NBLOCKS   (NGROUPS * SPLIT) // 400  (<= 592 conc @ occ 4 -> one wave)
#define W_IMG     28
#define NTHREADS  256
#define NWARPS    (NTHREADS / 32)   // 8

__device__ float        g_partials[NOUT * SPLIT];
__device__ unsigned int g_ticket = 0;

// 6250 = 8*781 + 2 -> first 2 chunks have 782 float8, rest 781
__device__ __forceinline__ int chunk_start(int c) { return c * 781 + (c < 2 ? c : 2); }

// 32-byte read-only load with L2 evict_last priority.
__device__ __forceinline__ void ldg32_el(const float* a, float f[8]) {
    uint64_t r0, r1, r2, r3;
    asm("ld.global.nc.L2::evict_last.v4.b64 {%0, %1, %2, %3}, [%4];"
        : "=l"(r0), "=l"(r1), "=l"(r2), "=l"(r3)
        : "l"(a));
    f[0] = __uint_as_float((uint32_t)r0); f[1] = __uint_as_float((uint32_t)(r0 >> 32));
    f[2] = __uint_as_float((uint32_t)r1); f[3] = __uint_as_float((uint32_t)(r1 >> 32));
    f[4] = __uint_as_float((uint32_t)r2); f[5] = __uint_as_float((uint32_t)(r2 >> 32));
    f[6] = __uint_as_float((uint32_t)r3); f[7] = __uint_as_float((uint32_t)(r3 >> 32));
}

__global__ __launch_bounds__(NTHREADS, 4)
void gather_dot_v11(const float* __restrict__ p,
                    const float* __restrict__ I,
                    const float* __restrict__ J,
                    const int*   __restrict__ inds1,
                    const int*   __restrict__ inds2,
                    float*       __restrict__ out)
{
    const int group = blockIdx.x / SPLIT;   // 0..49
    const int chunk = blockIdx.x % SPLIT;   // 0..7
    const int mbase = group * RPB;          // never straddles the I/J boundary

    const float* mat;
    const int*   ind;
    if (mbase < CARD2) { mat = I; ind = inds1 + 2 * mbase; }
    else               { mat = J; ind = inds2 + 2 * (mbase - CARD2); }

    const float* r0; const float* r1; const float* r2; const float* r3;
    {
        int row0 = __ldg(&ind[0]) * W_IMG + __ldg(&ind[1]);
        int row1 = __ldg(&ind[2]) * W_IMG + __ldg(&ind[3]);
        int row2 = __ldg(&ind[4]) * W_IMG + __ldg(&ind[5]);
        int row3 = __ldg(&ind[6]) * W_IMG + __ldg(&ind[7]);
        r0 = mat + (size_t)row0 * P_DIM;
        r1 = mat + (size_t)row1 * P_DIM;
        r2 = mat + (size_t)row2 * P_DIM;
        r3 = mat + (size_t)row3 * P_DIM;
    }

    const int c0 = chunk_start(chunk);
    const int c1 = chunk_start(chunk + 1);

    float s0 = 0.0f, s1 = 0.0f, s2 = 0.0f, s3 = 0.0f;

    // ~781 float8 / 256 threads -> ~3 iterations; 5 independent 32B loads/iter.
    for (int i = c0 + (int)threadIdx.x; i < c1; i += NTHREADS) {
        const size_t off = (size_t)i * 8;
        float pv[8], a0[8], a1[8], a2[8], a3[8];
        ldg32_el(p  + off, pv);
        ldg32_el(r0 + off, a0);
        ldg32_el(r1 + off, a1);
        ldg32_el(r2 + off, a2);
        ldg32_el(r3 + off, a3);
        #pragma unroll
        for (int k = 0; k < 8; k++) {
            s0 += a0[k] * pv[k];
            s1 += a1[k] * pv[k];
            s2 += a2[k] * pv[k];
            s3 += a3[k] * pv[k];
        }
    }

    // Warp reduction of the 4 accumulators
    #pragma unroll
    for (int off = 16; off > 0; off >>= 1) {
        s0 += __shfl_xor_sync(0xFFFFFFFFu, s0, off);
        s1 += __shfl_xor_sync(0xFFFFFFFFu, s1, off);
        s2 += __shfl_xor_sync(0xFFFFFFFFu, s2, off);
        s3 += __shfl_xor_sync(0xFFFFFFFFu, s3, off);
    }

    __shared__ float ws[RPB][NWARPS];
    __shared__ bool  s_last;
    const int lane = threadIdx.x & 31;
    const int wid  = threadIdx.x >> 5;
    if (lane == 0) { ws[0][wid] = s0; ws[1][wid] = s1; ws[2][wid] = s2; ws[3][wid] = s3; }
    __syncthreads();

    // Warps 0..3 each finish one accumulator (8 values -> 1)
    if (wid < RPB && lane < NWARPS) {
        float v = ws[wid][lane];
        #pragma unroll
        for (int off = NWARPS / 2; off > 0; off >>= 1)
            v += __shfl_xor_sync(0xFFu, v, off);
        if (lane == 0)
            g_partials[(mbase + wid) * SPLIT + chunk] = v;
    }

    // Fused final reduction: last block to finish sums the partials.
    __threadfence();
    if (threadIdx.x == 0) {
        unsigned int t = atomicAdd(&g_ticket, 1u);
        s_last = (t == NBLOCKS - 1);
    }
    __syncthreads();

    if (s_last) {
        const int m = threadIdx.x;
        if (m < NOUT) {
            float s = 0.0f;
            #pragma unroll
            for (int c = 0; c < SPLIT; c++)
                s += __ldcg(&g_partials[m * SPLIT + c]);
            out[m] = s;
        }
        if (threadIdx.x == 0) g_ticket = 0;   // reset for next call
    }
}

extern "C" void kernel_launch(void* const* d_in, const int* in_sizes, int n_in,
                              void* d_out, int out_size)
{
    const float* p     = (const float*)d_in[0];   // [50000]
    const float* I     = (const float*)d_in[1];   // [784, 50000]
    const float* J     = (const float*)d_in[2];   // [784, 50000]
    const int*   inds1 = (const int*)  d_in[3];   // [100, 2]
    const int*   inds2 = (const int*)  d_in[4];   // [100, 2]
    float*       out   = (float*)d_out;           // [200]

    gather_dot_v11<<<NBLOCKS, NTHREADS>>>(p, I, J, inds1, inds2, out);
}

// round 13
// speedup vs baseline: 1.0208x; 1.0208x over previous
#include <cuda_runtime.h>
#include <cstdint>

// out[0:100]   = dot(I[row,:], p), row = inds1[m,0]*28 + inds1[m,1]
// out[100:200] = dot(J[row,:], p), P = 50000.
//
// v12: deep TMA pipeline. 100 blocks (single wave), 5 streams/block
// (4 rows + p), 12KB bulk copies, 3-stage ring (2 stages of lookahead,
// ~120KB in flight per block). Compute reads SMEM only. Fused last-block
// reduction, single launch.

#define P_DIM     50000
#define P_VEC4    (P_DIM / 4)     // 12500 float4 per row
#define SPLIT     2
#define CHUNK4    (P_VEC4 / SPLIT) // 6250 float4 per stream per block
#define STAGE4    768              // float4 per stream per stage
#define NSTAGES   9                // 8*768 + 106
#define LAST4     (CHUNK4 - (NSTAGES - 1) * STAGE4)  // 106
#define CARD2     100
#define NOUT      200
#define RPB       4
#define NGROUPS   (NOUT / RPB)     // 50
#define NBLOCKS   (NGROUPS * SPLIT) // 100  (<= 148 -> one wave even at occ 1)
#define W_IMG     28
#define NTHREADS  512
#define NWARPS    16
#define NSTREAMS  (RPB + 1)
#define RING      3
#define STAGE_BYTES (STAGE4 * 16)                // 12288 B per stream
#define BUF_BYTES   (NSTREAMS * STAGE_BYTES)     // 61440 B per stage
#define SMEM_DYN    (RING * BUF_BYTES)           // 184320 B

__device__ float        g_partials[NOUT * SPLIT];
__device__ unsigned int g_ticket = 0;

__device__ __forceinline__ uint32_t smem_u32(const void* p) {
    uint32_t a;
    asm("{ .reg .u64 t; cvta.to.shared.u64 t, %1; cvt.u32.u64 %0, t; }"
        : "=r"(a) : "l"(p));
    return a;
}
__device__ __forceinline__ void mbar_init(uint32_t bar, uint32_t cnt) {
    asm volatile("mbarrier.init.shared.b64 [%0], %1;" :: "r"(bar), "r"(cnt) : "memory");
}
__device__ __forceinline__ void mbar_expect_tx(uint32_t bar, uint32_t bytes) {
    asm volatile("mbarrier.arrive.expect_tx.shared.b64 _, [%0], %1;"
                 :: "r"(bar), "r"(bytes) : "memory");
}
__device__ __forceinline__ void mbar_wait(uint32_t bar, uint32_t parity) {
    uint32_t done;
    asm volatile(
        "{ .reg .pred p;\n"
        "  mbarrier.try_wait.parity.acquire.cta.shared::cta.b64 p, [%1], %2;\n"
        "  selp.b32 %0, 1, 0, p; }"
        : "=r"(done) : "r"(bar), "r"(parity) : "memory");
    if (!done) {
        asm volatile(
            "{ .reg .pred P1;\n"
            "WAIT_%=:\n"
            "  mbarrier.try_wait.parity.acquire.cta.shared::cta.b64 P1, [%0], %1, 0x989680;\n"
            "  @P1 bra.uni DONE_%=;\n"
            "  bra.uni WAIT_%=;\n"
            "DONE_%=: }"
            :: "r"(bar), "r"(parity) : "memory");
    }
}
__device__ __forceinline__ void bulk_g2s(uint32_t dst, const void* src,
                                         uint32_t bytes, uint32_t bar) {
    asm volatile(
        "cp.async.bulk.shared::cta.global.mbarrier::complete_tx::bytes "
        "[%0], [%1], %2, [%3];"
        :: "r"(dst), "l"(src), "r"(bytes), "r"(bar) : "memory");
}

__global__ __launch_bounds__(NTHREADS)
void gather_dot_v12(const float* __restrict__ p,
                    const float* __restrict__ I,
                    const float* __restrict__ J,
                    const int*   __restrict__ inds1,
                    const int*   __restrict__ inds2,
                    float*       __restrict__ out)
{
    extern __shared__ __align__(128) unsigned char smem[];
    __shared__ __align__(8) uint64_t mbar_storage[RING];
    __shared__ float ws[RPB][NWARPS];
    __shared__ bool  s_last;

    const int tid   = threadIdx.x;
    const int group = blockIdx.x / SPLIT;   // 0..49
    const int chunk = blockIdx.x % SPLIT;   // 0..1
    const int mbase = group * RPB;          // never straddles the I/J boundary

    const float* mat;
    const int*   ind;
    if (mbase < CARD2) { mat = I; ind = inds1 + 2 * mbase; }
    else               { mat = J; ind = inds2 + 2 * (mbase - CARD2); }

    const uint32_t sbase = smem_u32(smem);
    uint32_t bar[RING];
    #pragma unroll
    for (int k = 0; k < RING; k++) bar[k] = smem_u32(&mbar_storage[k]);

    if (tid == 0) {
        #pragma unroll
        for (int k = 0; k < RING; k++) mbar_init(bar[k], 1);
    }
    __syncthreads();

    // Global byte-address source pointers, offset to this chunk.
    const char* src[NSTREAMS];
    #pragma unroll
    for (int k = 0; k < RPB; k++) {
        int row = ind[2 * k] * W_IMG + ind[2 * k + 1];
        src[k] = (const char*)(mat + (size_t)row * P_DIM) + (size_t)chunk * CHUNK4 * 16;
    }
    src[RPB] = (const char*)p + (size_t)chunk * CHUNK4 * 16;

    // Issue stage s into ring slot s%RING.
    auto issue = [&](int s) {
        const int      len   = (s == NSTAGES - 1) ? LAST4 : STAGE4;
        const uint32_t bytes = (uint32_t)len * 16u;
        const int      slot  = s % RING;
        const uint32_t dst0  = sbase + (uint32_t)slot * BUF_BYTES;
        mbar_expect_tx(bar[slot], bytes * NSTREAMS);
        #pragma unroll
        for (int k = 0; k < NSTREAMS; k++)
            bulk_g2s(dst0 + k * STAGE_BYTES, src[k] + (size_t)s * STAGE_BYTES,
                     bytes, bar[slot]);
    };

    if (tid == 0) { issue(0); issue(1); issue(2); }

    float s0 = 0.0f, s1 = 0.0f, s2 = 0.0f, s3 = 0.0f;

    for (int s = 0; s < NSTAGES; s++) {
        const int slot   = s % RING;
        const int parity = (s / RING) & 1;
        mbar_wait(bar[slot], parity);

        const int len = (s == NSTAGES - 1) ? LAST4 : STAGE4;
        const float4* buf = reinterpret_cast<const float4*>(smem + slot * BUF_BYTES);
        for (int i = tid; i < len; i += NTHREADS) {
            float4 pv = buf[4 * STAGE4 + i];
            float4 a0 = buf[0 * STAGE4 + i];
            float4 a1 = buf[1 * STAGE4 + i];
            float4 a2 = buf[2 * STAGE4 + i];
            float4 a3 = buf[3 * STAGE4 + i];
            s0 += a0.x * pv.x + a0.y * pv.y + a0.z * pv.z + a0.w * pv.w;
            s1 += a1.x * pv.x + a1.y * pv.y + a1.z * pv.z + a1.w * pv.w;
            s2 += a2.x * pv.x + a2.y * pv.y + a2.z * pv.z + a2.w * pv.w;
            s3 += a3.x * pv.x + a3.y * pv.y + a3.z * pv.z + a3.w * pv.w;
        }
        __syncthreads();                       // slot free for reuse
        if (tid == 0 && s + RING < NSTAGES) issue(s + RING);
    }

    // Warp reduction of the 4 accumulators
    #pragma unroll
    for (int off = 16; off > 0; off >>= 1) {
        s0 += __shfl_xor_sync(0xFFFFFFFFu, s0, off);
        s1 += __shfl_xor_sync(0xFFFFFFFFu, s1, off);
        s2 += __shfl_xor_sync(0xFFFFFFFFu, s2, off);
        s3 += __shfl_xor_sync(0xFFFFFFFFu, s3, off);
    }

    const int lane = tid & 31;
    const int wid  = tid >> 5;
    if (lane == 0) { ws[0][wid] = s0; ws[1][wid] = s1; ws[2][wid] = s2; ws[3][wid] = s3; }
    __syncthreads();

    if (wid < RPB && lane < NWARPS) {
        float v = ws[wid][lane];
        #pragma unroll
        for (int off = NWARPS / 2; off > 0; off >>= 1)
            v += __shfl_xor_sync(0xFFFFu, v, off);
        if (lane == 0)
            g_partials[(mbase + wid) * SPLIT + chunk] = v;
    }

    // Fused final reduction: last block to finish sums the partials.
    __threadfence();
    if (tid == 0) {
        unsigned int t = atomicAdd(&g_ticket, 1u);
        s_last = (t == NBLOCKS - 1);
    }
    __syncthreads();

    if (s_last) {
        const int m = tid;
        if (m < NOUT) {
            float s = 0.0f;
            #pragma unroll
            for (int c = 0; c < SPLIT; c++)
                s += __ldcg(&g_partials[m * SPLIT + c]);
            out[m] = s;
        }
        if (tid == 0) g_ticket = 0;   // reset for next call
    }
}

extern "C" void kernel_launch(void* const* d_in, const int* in_sizes, int n_in,
                              void* d_out, int out_size)
{
    const float* p     = (const float*)d_in[0];   // [50000]
    const float* I     = (const float*)d_in[1];   // [784, 50000]
    const float* J     = (const float*)d_in[2];   // [784, 50000]
    const int*   inds1 = (const int*)  d_in[3];   // [100, 2]
    const int*   inds2 = (const int*)  d_in[4];   // [100, 2]
    float*       out   = (float*)d_out;           // [200]

    cudaFuncSetAttribute(gather_dot_v12,
                         cudaFuncAttributeMaxDynamicSharedMemorySize, SMEM_DYN);
    gather_dot_v12<<<NBLOCKS, NTHREADS, SMEM_DYN>>>(p, I, J, inds1, inds2, out);
}